// round 1
// baseline (speedup 1.0000x reference)
#include <cuda_runtime.h>

// Problem constants
#define BV 8
#define GV 1024
#define NV 1022            // interior size
#define NPTS (BV * NV * NV)

// Scratch (static device globals — no runtime allocation allowed)
__device__ float g_bufA[NPTS];
__device__ float g_bufB[NPTS];
__device__ float g_inv [NPTS];   // 1 / y3
__device__ float g_fp  [NPTS];   // force * H^2 / y3

// ---------------------------------------------------------------------------
// Precompute: inv_y3 and scaled force (iteration-invariant)
// ---------------------------------------------------------------------------
__global__ void precompute_kernel(const float* __restrict__ f,
                                  const float* __restrict__ kappa) {
    int j = blockIdx.x * blockDim.x + threadIdx.x;
    int i = blockIdx.y;
    int b = blockIdx.z;
    if (j >= NV) return;

    const float* K = kappa + (size_t)b * GV * GV;
    float kc = K[(size_t)(i + 1) * GV + (j + 1)];
    float kN = K[(size_t)(i    ) * GV + (j + 1)];
    float kS = K[(size_t)(i + 2) * GV + (j + 1)];
    float kW = K[(size_t)(i + 1) * GV + (j    )];
    float kE = K[(size_t)(i + 1) * GV + (j + 2)];

    float y3  = 2.0f * kc + 0.5f * (kN + kS + kW + kE);
    float inv = __frcp_rn(y3);

    const float hh = (1.0f / 1023.0f) * (1.0f / 1023.0f);  // H^2, H = 1/(G-1)
    float force = f[(size_t)b * GV * GV + (size_t)(i + 1) * GV + (j + 1)] * hh;

    int idx = (b * NV + i) * NV + j;
    g_inv[idx] = inv;
    g_fp [idx] = force * inv;
}

// ---------------------------------------------------------------------------
// One Jacobi sweep:
//   u' = fp + 0.5 * inv * [ (kc+kN)uN + (kc+kS)uS + (kc+kW)uW + (kc+kE)uE ]
// Zero Dirichlet boundary (padded halo of the 1022x1022 interior is 0).
// ---------------------------------------------------------------------------
__global__ void jacobi_kernel(const float* __restrict__ uin,
                              float*       __restrict__ uout,
                              const float* __restrict__ kappa,
                              const float* __restrict__ inv,
                              const float* __restrict__ fp) {
    int j = blockIdx.x * blockDim.x + threadIdx.x;
    int i = blockIdx.y;
    int b = blockIdx.z;
    if (j >= NV) return;

    const float* K = kappa + (size_t)b * GV * GV + (size_t)(i + 1) * GV + (j + 1);
    float kc = K[0];
    float kN = K[-GV];
    float kS = K[ GV];
    float kW = K[-1];
    float kE = K[ 1];

    size_t idx = ((size_t)b * NV + i) * NV + j;
    const float* U = uin + idx;

    float uN = (i > 0     ) ? U[-NV] : 0.0f;
    float uS = (i < NV - 1) ? U[ NV] : 0.0f;
    float uW = (j > 0     ) ? U[-1 ] : 0.0f;
    float uE = (j < NV - 1) ? U[ 1 ] : 0.0f;

    float s = (kc + kN) * uN;
    s = fmaf(kc + kW, uW, s);
    s = fmaf(kc + kE, uE, s);
    s = fmaf(kc + kS, uS, s);

    uout[idx] = fmaf(0.5f * s, inv[idx], fp[idx]);
}

// ---------------------------------------------------------------------------
// kernel_launch: precompute + 16 ping-ponged sweeps, last sweep writes d_out.
// Graph-capturable: only kernel launches (cudaGetSymbolAddress is a pure
// address query, no stream work, no allocation).
// ---------------------------------------------------------------------------
extern "C" void kernel_launch(void* const* d_in, const int* in_sizes, int n_in,
                              void* d_out, int out_size) {
    const float* pre   = (const float*)d_in[0];   // (8,1,1022,1022)
    const float* f     = (const float*)d_in[1];   // (8,1,1024,1024)
    const float* kappa = (const float*)d_in[2];   // (8,1,1024,1024)
    float* out = (float*)d_out;                   // (8,1,1022,1022)

    float *A, *B, *inv, *fp;
    cudaGetSymbolAddress((void**)&A,   g_bufA);
    cudaGetSymbolAddress((void**)&B,   g_bufB);
    cudaGetSymbolAddress((void**)&inv, g_inv);
    cudaGetSymbolAddress((void**)&fp,  g_fp);

    dim3 blk(256, 1, 1);
    dim3 grd((NV + 255) / 256, NV, BV);

    precompute_kernel<<<grd, blk>>>(f, kappa);

    const float* src = pre;
    float* dst = A;
    for (int it = 0; it < 16; ++it) {
        float* d = (it == 15) ? out : dst;
        jacobi_kernel<<<grd, blk>>>(src, d, kappa, inv, fp);
        src = d;
        dst = (d == A) ? B : A;
    }
}

// round 2
// speedup vs baseline: 1.8813x; 1.8813x over previous
#include <cuda_runtime.h>

#define BV 8
#define GV 1024
#define NV 1022            // interior size
#define SP 1024            // padded row stride for scratch (16B-aligned rows)

// 2*H^2, H = 1/(G-1) = 1/1023
#define HH2 (2.0f / (1023.0f * 1023.0f))

// Ping-pong scratch, padded stride (no runtime allocation allowed)
__device__ __align__(256) float g_bufA[BV * NV * SP];
__device__ __align__(256) float g_bufB[BV * NV * SP];

__device__ __forceinline__ float4 ld4(const float* p) {
    return *reinterpret_cast<const float4*>(p);
}

// ---------------------------------------------------------------------------
// One Jacobi sweep, 4 points per thread along x.
//   numerator coeffs a_n = kc + k_n ; denom y3*2 = a_N+a_S+a_W+a_E
//   u' = (2*H^2*f + sum a_n*u_n) / (a_N+a_S+a_W+a_E)
// VIN/VOUT select vectorized (aligned, padded-stride) vs scalar access.
// ---------------------------------------------------------------------------
template<bool VIN, bool VOUT>
__global__ __launch_bounds__(128)
void sweep_kernel(const float* __restrict__ uin, int sin,
                  float*       __restrict__ uout, int sout,
                  const float* __restrict__ kappa,
                  const float* __restrict__ f)
{
    int j0 = 4 * (blockIdx.x * blockDim.x + threadIdx.x);
    int i  = blockIdx.y;
    int b  = blockIdx.z;
    if (j0 >= NV) return;

    // ---- kappa rows (full grid, center row = i+1), cols j0 .. j0+7 ----
    const float* Kc = kappa + (size_t)b * GV * GV + (size_t)(i + 1) * GV + j0;
    float4 kc0 = ld4(Kc),      kc1 = ld4(Kc + 4);
    float4 kn0 = ld4(Kc - GV), kn1 = ld4(Kc - GV + 4);
    float4 ks0 = ld4(Kc + GV), ks1 = ld4(Kc + GV + 4);
    const float* Fr = f + (size_t)b * GV * GV + (size_t)(i + 1) * GV + j0;
    float4 f0 = ld4(Fr), f1 = ld4(Fr + 4);

    float kcen[6] = {kc0.x, kc0.y, kc0.z, kc0.w, kc1.x, kc1.y}; // cols j0-? : col j0+m
    float kN[4]   = {kn0.y, kn0.z, kn0.w, kn1.x};               // col j0+1+l
    float kS[4]   = {ks0.y, ks0.z, ks0.w, ks1.x};
    float fv[4]   = {f0.y,  f0.z,  f0.w,  f1.x};

    // ---- u rows: uc covers cols j0-1 .. j0+4 ----
    float uN[4], uS[4], uc[6];
    if (VIN) {
        const float* Ur = uin + ((size_t)b * NV + i) * sin + j0;
        if (i > 0) {
            float4 t = ld4(Ur - sin);
            uN[0] = t.x; uN[1] = t.y; uN[2] = t.z; uN[3] = t.w;
        } else { uN[0] = uN[1] = uN[2] = uN[3] = 0.f; }
        if (i < NV - 1) {
            float4 t = ld4(Ur + sin);
            uS[0] = t.x; uS[1] = t.y; uS[2] = t.z; uS[3] = t.w;
        } else { uS[0] = uS[1] = uS[2] = uS[3] = 0.f; }
        float4 t = ld4(Ur);
        uc[1] = t.x; uc[2] = t.y; uc[3] = t.z; uc[4] = t.w;
        uc[0] = (j0 > 0)       ? Ur[-1] : 0.f;
        uc[5] = (j0 + 4 < NV)  ? Ur[4]  : 0.f;
    } else {
        const float* Ub = uin + ((size_t)b * NV + i) * sin;
        #pragma unroll
        for (int l = 0; l < 4; ++l) {
            int j = j0 + l;
            bool v = (j < NV);
            uN[l] = (v && i > 0)      ? Ub[- (size_t)sin + j] : 0.f;
            uS[l] = (v && i < NV - 1) ? Ub[  (size_t)sin + j] : 0.f;
        }
        #pragma unroll
        for (int m = 0; m < 6; ++m) {
            int c = j0 - 1 + m;
            uc[m] = (c >= 0 && c < NV) ? Ub[c] : 0.f;
        }
    }

    // ---- compute ----
    float res[4];
    #pragma unroll
    for (int l = 0; l < 4; ++l) {
        int j = j0 + l;
        float kcv = kcen[l + 1];
        float aN = kcv + kN[l];
        float aS = kcv + kS[l];
        float aW = kcv + kcen[l];
        float aE = kcv + kcen[l + 2];
        float uE = (j < NV - 1) ? uc[l + 2] : 0.f;   // zero Dirichlet at right edge
        float s = aN * uN[l];
        s = fmaf(aS, uS[l], s);
        s = fmaf(aW, uc[l], s);
        s = fmaf(aE, uE,    s);
        float denom = (aN + aS) + (aW + aE);
        float t = fmaf(fv[l], HH2, s);
        res[l] = t * __frcp_rn(denom);
    }

    // ---- store ----
    float* Or = uout + ((size_t)b * NV + i) * sout + j0;
    if (VOUT && (j0 + 4 <= NV)) {
        *reinterpret_cast<float4*>(Or) = make_float4(res[0], res[1], res[2], res[3]);
    } else {
        #pragma unroll
        for (int l = 0; l < 4; ++l)
            if (j0 + l < NV) Or[l] = res[l];
    }
}

// ---------------------------------------------------------------------------
// 16 sweeps: sweep 0 reads `pre` (stride 1022, scalar), middle sweeps
// ping-pong on padded scratch (vectorized), sweep 15 writes d_out (scalar out).
// ---------------------------------------------------------------------------
extern "C" void kernel_launch(void* const* d_in, const int* in_sizes, int n_in,
                              void* d_out, int out_size) {
    const float* pre   = (const float*)d_in[0];   // (8,1,1022,1022)
    const float* f     = (const float*)d_in[1];   // (8,1,1024,1024)
    const float* kappa = (const float*)d_in[2];   // (8,1,1024,1024)
    float* out = (float*)d_out;                   // (8,1,1022,1022)

    float *A, *B;
    cudaGetSymbolAddress((void**)&A, g_bufA);
    cudaGetSymbolAddress((void**)&B, g_bufB);

    dim3 blk(128, 1, 1);
    dim3 grd((NV + 4 * 128 - 1) / (4 * 128), NV, BV);   // (2, 1022, 8)

    // sweep 0: pre -> A
    sweep_kernel<false, true><<<grd, blk>>>(pre, NV, A, SP, kappa, f);

    // sweeps 1..14: padded ping-pong
    const float* src = A;
    float* dst = B;
    for (int it = 1; it < 15; ++it) {
        sweep_kernel<true, true><<<grd, blk>>>(src, SP, dst, SP, kappa, f);
        const float* t = dst; dst = (float*)src; src = t;
    }

    // sweep 15: -> d_out (stride 1022, scalar stores)
    sweep_kernel<true, false><<<grd, blk>>>(src, SP, out, NV, kappa, f);
}